// round 1
// baseline (speedup 1.0000x reference)
#include <cuda_runtime.h>
#include <cuda_bf16.h>
#include <math.h>

// Problem constants
#define NN   20000
#define EE   320000
#define HH   4

// ---------------- scratch (static __device__, no allocs) ----------------
__device__ float g_fs[NN * 512];       // source projection  [N, H*D] (max 512)
__device__ float g_fd[NN * 512];       // dest   projection
__device__ float g_h1[NN * 128];       // layer intermediate outputs
__device__ float g_h2[NN * 128];
__device__ int   g_cnt[NN];
__device__ int   g_cursor[NN];
__device__ int   g_rowptr[NN + 1];
__device__ int   g_csrsrc[EE];

// ---------------- CSR build ----------------
__global__ void hist_kernel(const int* __restrict__ dst, int* __restrict__ cnt, int E) {
    int e = blockIdx.x * blockDim.x + threadIdx.x;
    if (e < E) atomicAdd(&cnt[dst[e]], 1);
}

// single-block exclusive scan: rowptr[0]=0, rowptr[i+1]=sum(cnt[0..i])
__global__ void scan_kernel(const int* __restrict__ cnt, int* __restrict__ rowptr, int n) {
    __shared__ int smem[1024];
    __shared__ int carry;
    int tid = threadIdx.x;
    if (tid == 0) { carry = 0; rowptr[0] = 0; }
    __syncthreads();
    for (int base = 0; base < n; base += 1024) {
        int c = carry;
        __syncthreads();
        int i = base + tid;
        int v = (i < n) ? cnt[i] : 0;
        smem[tid] = v;
        __syncthreads();
        for (int off = 1; off < 1024; off <<= 1) {
            int t = (tid >= off) ? smem[tid - off] : 0;
            __syncthreads();
            smem[tid] += t;
            __syncthreads();
        }
        if (i < n) rowptr[i + 1] = smem[tid] + c;
        __syncthreads();
        if (tid == 0) carry = c + smem[1023];
        __syncthreads();
    }
}

__global__ void scatter_kernel(const int* __restrict__ src, const int* __restrict__ dst,
                               const int* __restrict__ rowptr, int* __restrict__ cursor,
                               int* __restrict__ csrsrc, int E) {
    int e = blockIdx.x * blockDim.x + threadIdx.x;
    if (e < E) {
        int d = dst[e];
        int pos = rowptr[d] + atomicAdd(&cursor[d], 1);
        csrsrc[pos] = src[e];
    }
}

// ---------------- GEMM: C[M,N] = A[M,K] @ B[K,N]   (fp32 tiled) ----------------
// BM=64, BN=64, BK=16; 256 threads, 4x4 per thread. N % 64 == 0, K % 16 == 0; M guarded.
__global__ void gemm_kernel(const float* __restrict__ A, const float* __restrict__ B,
                            float* __restrict__ C, int M, int N, int K) {
    __shared__ float As[16][64];   // [k][m]
    __shared__ float Bs[16][64];   // [k][n]

    int tid = threadIdx.x;
    int mbase = blockIdx.y * 64;
    int nbase = blockIdx.x * 64;
    int ty = tid / 16;             // 0..15 -> m sub-tile
    int tx = tid % 16;             // 0..15 -> n sub-tile

    float c[4][4];
#pragma unroll
    for (int i = 0; i < 4; i++)
#pragma unroll
        for (int j = 0; j < 4; j++) c[i][j] = 0.f;

    // A tile loader coords: 64 rows x 16 k, as float4 along k
    int arow = tid / 4;            // 0..63
    int akq  = tid % 4;            // 0..3 (float4 index along k)
    // B tile loader coords: 16 rows(k) x 64 n, as float4 along n
    int brow = tid / 16;           // 0..15
    int bnq  = tid % 16;           // 0..15

    for (int k0 = 0; k0 < K; k0 += 16) {
        // load A
        float4 av = make_float4(0.f, 0.f, 0.f, 0.f);
        int gm = mbase + arow;
        if (gm < M) av = *reinterpret_cast<const float4*>(&A[(long)gm * K + k0 + akq * 4]);
        As[akq * 4 + 0][arow] = av.x;
        As[akq * 4 + 1][arow] = av.y;
        As[akq * 4 + 2][arow] = av.z;
        As[akq * 4 + 3][arow] = av.w;
        // load B
        float4 bv = *reinterpret_cast<const float4*>(&B[(long)(k0 + brow) * N + nbase + bnq * 4]);
        *reinterpret_cast<float4*>(&Bs[brow][bnq * 4]) = bv;
        __syncthreads();

#pragma unroll
        for (int k = 0; k < 16; k++) {
            float4 a = *reinterpret_cast<float4*>(&As[k][ty * 4]);
            float4 b = *reinterpret_cast<float4*>(&Bs[k][tx * 4]);
            float ar[4] = {a.x, a.y, a.z, a.w};
            float br[4] = {b.x, b.y, b.z, b.w};
#pragma unroll
            for (int i = 0; i < 4; i++)
#pragma unroll
                for (int j = 0; j < 4; j++) c[i][j] += ar[i] * br[j];
        }
        __syncthreads();
    }

#pragma unroll
    for (int i = 0; i < 4; i++) {
        int gm = mbase + ty * 4 + i;
        if (gm < M) {
#pragma unroll
            for (int j = 0; j < 4; j++)
                C[(long)gm * N + nbase + tx * 4 + j] = c[i][j];
        }
    }
}

// ---------------- fused GATv2 aggregation per destination node ----------------
// block = 128 threads = 4 warps; warp h handles head h of node v (one block per node).
// Online softmax over in-edges; fuses logit, softmax, weighted sum, bias, head-mean, lrelu.
template <int D>
__global__ void gat_agg_kernel(const float* __restrict__ fs, const float* __restrict__ fd,
                               const float* __restrict__ attn, const float* __restrict__ bias,
                               const int* __restrict__ rowptr, const int* __restrict__ csrsrc,
                               float* __restrict__ hout) {
    constexpr int VPT = D / 32;
    constexpr int HD = HH * D;
    int v = blockIdx.x;
    int h = threadIdx.x >> 5;
    int lane = threadIdx.x & 31;

    float fdv[VPT], at[VPT], acc[VPT];
    int base = v * HD + h * D;
#pragma unroll
    for (int j = 0; j < VPT; j++) {
        int d = j * 32 + lane;
        fdv[j] = fd[base + d];
        at[j]  = attn[h * D + d];
        acc[j] = 0.f;
    }
    float m = -INFINITY, s = 0.f;

    int e0 = rowptr[v], e1 = rowptr[v + 1];
    for (int e = e0; e < e1; e++) {
        int u = csrsrc[e];
        int ub = u * HD + h * D;
        float x[VPT];
        float p = 0.f;
#pragma unroll
        for (int j = 0; j < VPT; j++) {
            int d = j * 32 + lane;
            x[j] = fs[ub + d];
            float t = x[j] + fdv[j];
            t = (t > 0.f) ? t : 0.2f * t;   // GATv2 internal leaky_relu
            p += t * at[j];
        }
#pragma unroll
        for (int off = 16; off; off >>= 1)
            p += __shfl_xor_sync(0xffffffffu, p, off);
        // online softmax update
        if (p > m) {
            float cc = __expf(m - p);       // first edge: m=-inf -> cc=0
            s = s * cc + 1.f;
#pragma unroll
            for (int j = 0; j < VPT; j++) acc[j] = acc[j] * cc + x[j];
            m = p;
        } else {
            float w = __expf(p - m);
            s += w;
#pragma unroll
            for (int j = 0; j < VPT; j++) acc[j] += w * x[j];
        }
    }

    __shared__ float hm[HH][D];
    float inv_s = (e1 > e0) ? (1.f / s) : 0.f;
#pragma unroll
    for (int j = 0; j < VPT; j++) {
        int d = j * 32 + lane;
        hm[h][d] = acc[j] * inv_s + bias[h * D + d];
    }
    __syncthreads();
    for (int d = threadIdx.x; d < D; d += blockDim.x) {
        float mv = 0.25f * (hm[0][d] + hm[1][d] + hm[2][d] + hm[3][d]);
        hout[v * D + d] = (mv > 0.f) ? mv : 0.01f * mv;  // ACT leaky_relu
    }
}

// ---------------- final mean over nodes: [N,64] -> [64] ----------------
__global__ void final_mean_kernel(const float* __restrict__ hin, float* __restrict__ out, int n) {
    int d = threadIdx.x;  // blockDim = 64
    float sum = 0.f;
    for (int r = blockIdx.x; r < n; r += gridDim.x)
        sum += hin[r * 64 + d];
    atomicAdd(&out[d], sum * (1.0f / (float)NN));
}

// ---------------- launch ----------------
extern "C" void kernel_launch(void* const* d_in, const int* in_sizes, int n_in,
                              void* d_out, int out_size) {
    const float* n_feat = (const float*)d_in[0];
    const int*   src    = (const int*)d_in[1];
    const int*   dst    = (const int*)d_in[2];
    const float* Wl0 = (const float*)d_in[3];
    const float* Wr0 = (const float*)d_in[4];
    const float* attn0 = (const float*)d_in[5];
    const float* b0 = (const float*)d_in[6];
    const float* Wl1 = (const float*)d_in[7];
    const float* Wr1 = (const float*)d_in[8];
    const float* attn1 = (const float*)d_in[9];
    const float* b1 = (const float*)d_in[10];
    const float* Wl2 = (const float*)d_in[11];
    const float* Wr2 = (const float*)d_in[12];
    const float* attn2 = (const float*)d_in[13];
    const float* b2 = (const float*)d_in[14];
    float* out = (float*)d_out;

    float *fs, *fd, *h1, *h2;
    int *cnt, *cursor, *rowptr, *csrsrc;
    cudaGetSymbolAddress((void**)&fs, g_fs);
    cudaGetSymbolAddress((void**)&fd, g_fd);
    cudaGetSymbolAddress((void**)&h1, g_h1);
    cudaGetSymbolAddress((void**)&h2, g_h2);
    cudaGetSymbolAddress((void**)&cnt, g_cnt);
    cudaGetSymbolAddress((void**)&cursor, g_cursor);
    cudaGetSymbolAddress((void**)&rowptr, g_rowptr);
    cudaGetSymbolAddress((void**)&csrsrc, g_csrsrc);

    const int N = NN, E = EE;

    // CSR build (graph fixed, but must redo every call: deterministic same work)
    cudaMemsetAsync(cnt, 0, N * sizeof(int));
    cudaMemsetAsync(cursor, 0, N * sizeof(int));
    hist_kernel<<<(E + 255) / 256, 256>>>(dst, cnt, E);
    scan_kernel<<<1, 1024>>>(cnt, rowptr, N);
    scatter_kernel<<<(E + 255) / 256, 256>>>(src, dst, rowptr, cursor, csrsrc, E);

    dim3 tb(256);
    int mblk = (N + 63) / 64;

    // ---- layer 0: 512 -> H x 128 ----
    gemm_kernel<<<dim3(512 / 64, mblk), tb>>>(n_feat, Wl0, fs, N, 512, 512);
    gemm_kernel<<<dim3(512 / 64, mblk), tb>>>(n_feat, Wr0, fd, N, 512, 512);
    gat_agg_kernel<128><<<N, 128>>>(fs, fd, attn0, b0, rowptr, csrsrc, h1);

    // ---- layer 1: 128 -> H x 128 ----
    gemm_kernel<<<dim3(512 / 64, mblk), tb>>>(h1, Wl1, fs, N, 512, 128);
    gemm_kernel<<<dim3(512 / 64, mblk), tb>>>(h1, Wr1, fd, N, 512, 128);
    gat_agg_kernel<128><<<N, 128>>>(fs, fd, attn1, b1, rowptr, csrsrc, h2);

    // ---- layer 2: 128 -> H x 64 ----
    gemm_kernel<<<dim3(256 / 64, mblk), tb>>>(h2, Wl2, fs, N, 256, 128);
    gemm_kernel<<<dim3(256 / 64, mblk), tb>>>(h2, Wr2, fd, N, 256, 128);
    gat_agg_kernel<64><<<N, 128>>>(fs, fd, attn2, b2, rowptr, csrsrc, h1);

    // ---- readout ----
    cudaMemsetAsync(out, 0, 64 * sizeof(float));
    final_mean_kernel<<<256, 64>>>(h1, out, N);
}

// round 2
// speedup vs baseline: 1.6385x; 1.6385x over previous
#include <cuda_runtime.h>
#include <cuda_bf16.h>
#include <math.h>
#include <stdint.h>

// Problem constants
#define NN   20000
#define EE   320000
#define HH   4

// ---------------- scratch (static __device__, no allocs) ----------------
__device__ float g_fs[NN * 512];       // source projection  [N, H*D] (max 512)
__device__ float g_fd[NN * 512];       // dest   projection
__device__ float g_h1[NN * 128];       // layer intermediate outputs
__device__ float g_h2[NN * 128];
__device__ int   g_cnt[NN];
__device__ int   g_cursor[NN];
__device__ int   g_rowptr[NN + 1];
__device__ int   g_csrsrc[EE];

// ---------------- CSR build ----------------
__global__ void hist_kernel(const int* __restrict__ dst, int* __restrict__ cnt, int E) {
    int e = blockIdx.x * blockDim.x + threadIdx.x;
    if (e < E) atomicAdd(&cnt[dst[e]], 1);
}

__global__ void scan_kernel(const int* __restrict__ cnt, int* __restrict__ rowptr, int n) {
    __shared__ int smem[1024];
    __shared__ int carry;
    int tid = threadIdx.x;
    if (tid == 0) { carry = 0; rowptr[0] = 0; }
    __syncthreads();
    for (int base = 0; base < n; base += 1024) {
        int c = carry;
        __syncthreads();
        int i = base + tid;
        int v = (i < n) ? cnt[i] : 0;
        smem[tid] = v;
        __syncthreads();
        for (int off = 1; off < 1024; off <<= 1) {
            int t = (tid >= off) ? smem[tid - off] : 0;
            __syncthreads();
            smem[tid] += t;
            __syncthreads();
        }
        if (i < n) rowptr[i + 1] = smem[tid] + c;
        __syncthreads();
        if (tid == 0) carry = c + smem[1023];
        __syncthreads();
    }
}

__global__ void scatter_kernel(const int* __restrict__ src, const int* __restrict__ dst,
                               const int* __restrict__ rowptr, int* __restrict__ cursor,
                               int* __restrict__ csrsrc, int E) {
    int e = blockIdx.x * blockDim.x + threadIdx.x;
    if (e < E) {
        int d = dst[e];
        int pos = rowptr[d] + atomicAdd(&cursor[d], 1);
        csrsrc[pos] = src[e];
    }
}

// ---------------- TF32 tensor-core GEMM ----------------
// C[M,N] = A[M,K] @ B[K,N], row-major. BM=128, BN=64, BK=16.
// 256 threads = 8 warps as 4(m) x 2(n); warp tile 32x32 = 2x4 m16n8k8 atoms.
// Requires N % 64 == 0, K % 16 == 0; M guarded.

__device__ __forceinline__ uint32_t f2tf32(float x) {
    uint32_t r;
    asm("cvt.rna.tf32.f32 %0, %1;" : "=r"(r) : "f"(x));
    return r;
}

__device__ __forceinline__ void mma_tf32(float* d, const uint32_t* a, const uint32_t* b) {
    asm volatile(
        "mma.sync.aligned.m16n8k8.row.col.f32.tf32.tf32.f32 "
        "{%0,%1,%2,%3}, {%4,%5,%6,%7}, {%8,%9}, {%0,%1,%2,%3};\n"
        : "+f"(d[0]), "+f"(d[1]), "+f"(d[2]), "+f"(d[3])
        : "r"(a[0]), "r"(a[1]), "r"(a[2]), "r"(a[3]), "r"(b[0]), "r"(b[1]));
}

#define BM 128
#define BN 64
#define BK 16
#define PADM 136   // 136 % 32 == 8 -> frag loads hit 32 distinct banks
#define PADN 72    // 72 % 32 == 8

__global__ __launch_bounds__(256) void gemm_tc_kernel(
        const float* __restrict__ A, const float* __restrict__ B,
        float* __restrict__ C, int M, int N, int K) {
    __shared__ uint32_t As[BK][PADM];   // [k][m], tf32 bits
    __shared__ uint32_t Bs[BK][PADN];   // [k][n]

    int tid  = threadIdx.x;
    int warp = tid >> 5, lane = tid & 31;
    int g = lane >> 2, t = lane & 3;          // groupID / threadID_in_group
    int mb = blockIdx.y * BM, nb = blockIdx.x * BN;
    int wm = (warp & 3) * 32, wn = (warp >> 2) * 32;

    float c[2][4][4];
#pragma unroll
    for (int i = 0; i < 2; i++)
#pragma unroll
        for (int j = 0; j < 4; j++)
#pragma unroll
            for (int r = 0; r < 4; r++) c[i][j][r] = 0.f;

    // A loader: 512 float4 per tile, 2 per thread (rows arow, arow+64)
    int arow = tid >> 2;           // 0..63
    int acol = (tid & 3) * 4;      // k offset (float4)
    // B loader: 256 float4 per tile, 1 per thread
    int brow = tid >> 4;           // 0..15 (k)
    int bcol = (tid & 15) * 4;     // n offset

    for (int k0 = 0; k0 < K; k0 += BK) {
#pragma unroll
        for (int rr = 0; rr < 2; rr++) {
            int r = arow + rr * 64;
            int gm = mb + r;
            float4 v = make_float4(0.f, 0.f, 0.f, 0.f);
            if (gm < M) v = *reinterpret_cast<const float4*>(&A[(long)gm * K + k0 + acol]);
            As[acol + 0][r] = f2tf32(v.x);
            As[acol + 1][r] = f2tf32(v.y);
            As[acol + 2][r] = f2tf32(v.z);
            As[acol + 3][r] = f2tf32(v.w);
        }
        {
            float4 v = *reinterpret_cast<const float4*>(&B[(long)(k0 + brow) * N + nb + bcol]);
            Bs[brow][bcol + 0] = f2tf32(v.x);
            Bs[brow][bcol + 1] = f2tf32(v.y);
            Bs[brow][bcol + 2] = f2tf32(v.z);
            Bs[brow][bcol + 3] = f2tf32(v.w);
        }
        __syncthreads();

#pragma unroll
        for (int ks = 0; ks < 2; ks++) {
            int kk = ks * 8;
            uint32_t a[2][4], b[4][2];
#pragma unroll
            for (int im = 0; im < 2; im++) {
                int row = wm + im * 16;
                a[im][0] = As[kk + t][row + g];
                a[im][1] = As[kk + t][row + g + 8];
                a[im][2] = As[kk + t + 4][row + g];
                a[im][3] = As[kk + t + 4][row + g + 8];
            }
#pragma unroll
            for (int jn = 0; jn < 4; jn++) {
                int col = wn + jn * 8 + g;
                b[jn][0] = Bs[kk + t][col];
                b[jn][1] = Bs[kk + t + 4][col];
            }
#pragma unroll
            for (int im = 0; im < 2; im++)
#pragma unroll
                for (int jn = 0; jn < 4; jn++)
                    mma_tf32(c[im][jn], a[im], b[jn]);
        }
        __syncthreads();
    }

    // store: c0 (g, 2t), c1 (g, 2t+1), c2 (g+8, 2t), c3 (g+8, 2t+1)
#pragma unroll
    for (int im = 0; im < 2; im++) {
#pragma unroll
        for (int jn = 0; jn < 4; jn++) {
            int col = nb + wn + jn * 8 + t * 2;
            int row0 = mb + wm + im * 16 + g;
            if (row0 < M) {
                C[(long)row0 * N + col]     = c[im][jn][0];
                C[(long)row0 * N + col + 1] = c[im][jn][1];
            }
            int row1 = row0 + 8;
            if (row1 < M) {
                C[(long)row1 * N + col]     = c[im][jn][2];
                C[(long)row1 * N + col + 1] = c[im][jn][3];
            }
        }
    }
}

// ---------------- fused GATv2 aggregation per destination node ----------------
template <int D>
__global__ void gat_agg_kernel(const float* __restrict__ fs, const float* __restrict__ fd,
                               const float* __restrict__ attn, const float* __restrict__ bias,
                               const int* __restrict__ rowptr, const int* __restrict__ csrsrc,
                               float* __restrict__ hout) {
    constexpr int VPT = D / 32;
    constexpr int HD = HH * D;
    int v = blockIdx.x;
    int h = threadIdx.x >> 5;
    int lane = threadIdx.x & 31;

    float fdv[VPT], at[VPT], acc[VPT];
    int base = v * HD + h * D;
#pragma unroll
    for (int j = 0; j < VPT; j++) {
        int d = j * 32 + lane;
        fdv[j] = fd[base + d];
        at[j]  = attn[h * D + d];
        acc[j] = 0.f;
    }
    float m = -INFINITY, s = 0.f;

    int e0 = rowptr[v], e1 = rowptr[v + 1];
    for (int e = e0; e < e1; e++) {
        int u = csrsrc[e];
        int ub = u * HD + h * D;
        float x[VPT];
        float p = 0.f;
#pragma unroll
        for (int j = 0; j < VPT; j++) {
            int d = j * 32 + lane;
            x[j] = fs[ub + d];
            float tt = x[j] + fdv[j];
            tt = (tt > 0.f) ? tt : 0.2f * tt;   // GATv2 internal leaky_relu
            p += tt * at[j];
        }
#pragma unroll
        for (int off = 16; off; off >>= 1)
            p += __shfl_xor_sync(0xffffffffu, p, off);
        if (p > m) {
            float cc = __expf(m - p);
            s = s * cc + 1.f;
#pragma unroll
            for (int j = 0; j < VPT; j++) acc[j] = acc[j] * cc + x[j];
            m = p;
        } else {
            float w = __expf(p - m);
            s += w;
#pragma unroll
            for (int j = 0; j < VPT; j++) acc[j] += w * x[j];
        }
    }

    __shared__ float hm[HH][D];
    float inv_s = (e1 > e0) ? (1.f / s) : 0.f;
#pragma unroll
    for (int j = 0; j < VPT; j++) {
        int d = j * 32 + lane;
        hm[h][d] = acc[j] * inv_s + bias[h * D + d];
    }
    __syncthreads();
    for (int d = threadIdx.x; d < D; d += blockDim.x) {
        float mv = 0.25f * (hm[0][d] + hm[1][d] + hm[2][d] + hm[3][d]);
        hout[v * D + d] = (mv > 0.f) ? mv : 0.01f * mv;  // ACT leaky_relu
    }
}

// ---------------- final mean over nodes: [N,64] -> [64] ----------------
__global__ void final_mean_kernel(const float* __restrict__ hin, float* __restrict__ out, int n) {
    int d = threadIdx.x;  // blockDim = 64
    float sum = 0.f;
    for (int r = blockIdx.x; r < n; r += gridDim.x)
        sum += hin[r * 64 + d];
    atomicAdd(&out[d], sum * (1.0f / (float)NN));
}

// ---------------- launch ----------------
extern "C" void kernel_launch(void* const* d_in, const int* in_sizes, int n_in,
                              void* d_out, int out_size) {
    const float* n_feat = (const float*)d_in[0];
    const int*   src    = (const int*)d_in[1];
    const int*   dst    = (const int*)d_in[2];
    const float* Wl0 = (const float*)d_in[3];
    const float* Wr0 = (const float*)d_in[4];
    const float* attn0 = (const float*)d_in[5];
    const float* b0 = (const float*)d_in[6];
    const float* Wl1 = (const float*)d_in[7];
    const float* Wr1 = (const float*)d_in[8];
    const float* attn1 = (const float*)d_in[9];
    const float* b1 = (const float*)d_in[10];
    const float* Wl2 = (const float*)d_in[11];
    const float* Wr2 = (const float*)d_in[12];
    const float* attn2 = (const float*)d_in[13];
    const float* b2 = (const float*)d_in[14];
    float* out = (float*)d_out;

    float *fs, *fd, *h1, *h2;
    int *cnt, *cursor, *rowptr, *csrsrc;
    cudaGetSymbolAddress((void**)&fs, g_fs);
    cudaGetSymbolAddress((void**)&fd, g_fd);
    cudaGetSymbolAddress((void**)&h1, g_h1);
    cudaGetSymbolAddress((void**)&h2, g_h2);
    cudaGetSymbolAddress((void**)&cnt, g_cnt);
    cudaGetSymbolAddress((void**)&cursor, g_cursor);
    cudaGetSymbolAddress((void**)&rowptr, g_rowptr);
    cudaGetSymbolAddress((void**)&csrsrc, g_csrsrc);

    const int N = NN, E = EE;

    cudaMemsetAsync(cnt, 0, N * sizeof(int));
    cudaMemsetAsync(cursor, 0, N * sizeof(int));
    hist_kernel<<<(E + 255) / 256, 256>>>(dst, cnt, E);
    scan_kernel<<<1, 1024>>>(cnt, rowptr, N);
    scatter_kernel<<<(E + 255) / 256, 256>>>(src, dst, rowptr, cursor, csrsrc, E);

    dim3 tb(256);
    int mblk = (N + BM - 1) / BM;   // 157

    // ---- layer 0: 512 -> H x 128 ----
    gemm_tc_kernel<<<dim3(512 / BN, mblk), tb>>>(n_feat, Wl0, fs, N, 512, 512);
    gemm_tc_kernel<<<dim3(512 / BN, mblk), tb>>>(n_feat, Wr0, fd, N, 512, 512);
    gat_agg_kernel<128><<<N, 128>>>(fs, fd, attn0, b0, rowptr, csrsrc, h1);

    // ---- layer 1: 128 -> H x 128 ----
    gemm_tc_kernel<<<dim3(512 / BN, mblk), tb>>>(h1, Wl1, fs, N, 512, 128);
    gemm_tc_kernel<<<dim3(512 / BN, mblk), tb>>>(h1, Wr1, fd, N, 512, 128);
    gat_agg_kernel<128><<<N, 128>>>(fs, fd, attn1, b1, rowptr, csrsrc, h2);

    // ---- layer 2 (output): 128 -> H x 64 ----
    gemm_tc_kernel<<<dim3(256 / BN, mblk), tb>>>(h2, Wl2, fs, N, 256, 128);
    gemm_tc_kernel<<<dim3(256 / BN, mblk), tb>>>(h2, Wr2, fd, N, 256, 128);
    gat_agg_kernel<64><<<N, 128>>>(fs, fd, attn2, b2, rowptr, csrsrc, h1);

    // ---- readout ----
    cudaMemsetAsync(out, 0, 64 * sizeof(float));
    final_mean_kernel<<<256, 64>>>(h1, out, N);
}

// round 3
// speedup vs baseline: 1.8817x; 1.1484x over previous
#include <cuda_runtime.h>
#include <cuda_bf16.h>
#include <math.h>
#include <stdint.h>

// Problem constants
#define NN   20000
#define EE   320000
#define HH   4

// ---------------- scratch (static __device__, no allocs) ----------------
__device__ float g_proj[NN * 1024];    // combined [fs | fd] projections, row stride = 2*H*D
__device__ float g_A0[NN * 512];       // tf32-rounded n_feat
__device__ float g_h1[NN * 128];       // layer intermediate outputs (tf32-rounded)
__device__ float g_h2[NN * 128];
__device__ float g_wbuf[720896];       // tf32-rounded weights, packed
__device__ int   g_cnt[NN];
__device__ int   g_cursor[NN];
__device__ int   g_rowptr[NN + 1];
__device__ int   g_csrsrc[EE];

// weight offsets in g_wbuf (floats)
#define OFF_WL0 0
#define OFF_WR0 262144
#define OFF_WL1 524288
#define OFF_WR1 589824
#define OFF_WL2 655360
#define OFF_WR2 688128

__device__ __forceinline__ uint32_t f2tf32(float x) {
    uint32_t r;
    asm("cvt.rna.tf32.f32 %0, %1;" : "=r"(r) : "f"(x));
    return r;
}
__device__ __forceinline__ float tf32r(float x) { return __uint_as_float(f2tf32(x)); }

// ---------------- tf32 pre-rounding (elementwise, n % 4 == 0) ----------------
__global__ void tf32_round_kernel(const float* __restrict__ in, float* __restrict__ out, int n) {
    int i = (blockIdx.x * blockDim.x + threadIdx.x) * 4;
    if (i < n) {
        float4 v = *reinterpret_cast<const float4*>(in + i);
        v.x = tf32r(v.x); v.y = tf32r(v.y); v.z = tf32r(v.z); v.w = tf32r(v.w);
        *reinterpret_cast<float4*>(out + i) = v;
    }
}

// ---------------- CSR build ----------------
__global__ void hist_kernel(const int* __restrict__ dst, int* __restrict__ cnt, int E) {
    int e = blockIdx.x * blockDim.x + threadIdx.x;
    if (e < E) atomicAdd(&cnt[dst[e]], 1);
}

__global__ void scan_kernel(const int* __restrict__ cnt, int* __restrict__ rowptr, int n) {
    __shared__ int smem[1024];
    __shared__ int carry;
    int tid = threadIdx.x;
    if (tid == 0) { carry = 0; rowptr[0] = 0; }
    __syncthreads();
    for (int base = 0; base < n; base += 1024) {
        int c = carry;
        __syncthreads();
        int i = base + tid;
        int v = (i < n) ? cnt[i] : 0;
        smem[tid] = v;
        __syncthreads();
        for (int off = 1; off < 1024; off <<= 1) {
            int t = (tid >= off) ? smem[tid - off] : 0;
            __syncthreads();
            smem[tid] += t;
            __syncthreads();
        }
        if (i < n) rowptr[i + 1] = smem[tid] + c;
        __syncthreads();
        if (tid == 0) carry = c + smem[1023];
        __syncthreads();
    }
}

__global__ void scatter_kernel(const int* __restrict__ src, const int* __restrict__ dst,
                               const int* __restrict__ rowptr, int* __restrict__ cursor,
                               int* __restrict__ csrsrc, int E) {
    int e = blockIdx.x * blockDim.x + threadIdx.x;
    if (e < E) {
        int d = dst[e];
        int pos = rowptr[d] + atomicAdd(&cursor[d], 1);
        csrsrc[pos] = src[e];
    }
}

// ---------------- TF32 tensor-core GEMM, cp.async double-buffered ----------------
// C[M, 2*Nh] = A[M,K] @ [Bl | Br] ([K,Nh] each), all row-major, pre-rounded to tf32.
// BM=128, BN=64, BK=32. 256 threads = 8 warps (4m x 2n), warp tile 32x32.
#define BM 128
#define BN 64
#define BK 32
#define AS_STRIDE 36   // words; 144B rows (16B-aligned), bank stride 4 -> frag banks 4g+t
#define BS_STRIDE 72   // words; 288B rows (16B-aligned), bank stride 8 -> frag banks 8t+g
#define AS_WORDS (BM * AS_STRIDE)   // 4608
#define BS_WORDS (BK * BS_STRIDE)   // 2304
#define SMEM_BYTES ((2 * AS_WORDS + 2 * BS_WORDS) * 4)   // 55296

__device__ __forceinline__ void cp16(float* dst, const float* src, bool p) {
    uint32_t d = (uint32_t)__cvta_generic_to_shared(dst);
    int sz = p ? 16 : 0;
    asm volatile("cp.async.cg.shared.global [%0], [%1], 16, %2;\n" :: "r"(d), "l"(src), "r"(sz));
}

__device__ __forceinline__ void mma_tf32(float* d, const uint32_t* a, const uint32_t* b) {
    asm volatile(
        "mma.sync.aligned.m16n8k8.row.col.f32.tf32.tf32.f32 "
        "{%0,%1,%2,%3}, {%4,%5,%6,%7}, {%8,%9}, {%0,%1,%2,%3};\n"
        : "+f"(d[0]), "+f"(d[1]), "+f"(d[2]), "+f"(d[3])
        : "r"(a[0]), "r"(a[1]), "r"(a[2]), "r"(a[3]), "r"(b[0]), "r"(b[1]));
}

__global__ __launch_bounds__(256) void gemm_tc2_kernel(
        const float* __restrict__ A, const float* __restrict__ Bl,
        const float* __restrict__ Br, float* __restrict__ C,
        int M, int Nh, int K) {
    extern __shared__ float smem[];
    const int Ntot = 2 * Nh;

    int tid  = threadIdx.x;
    int warp = tid >> 5, lane = tid & 31;
    int g = lane >> 2, t = lane & 3;
    int mb = blockIdx.y * BM;
    int nb = blockIdx.x * BN;
    const float* B = (nb < Nh) ? Bl : Br;
    int ncol = (nb < Nh) ? nb : nb - Nh;
    int wm = (warp & 3) * 32, wn = (warp >> 2) * 32;

    float c[2][4][4];
#pragma unroll
    for (int i = 0; i < 2; i++)
#pragma unroll
        for (int j = 0; j < 4; j++)
#pragma unroll
            for (int r = 0; r < 4; r++) c[i][j][r] = 0.f;

    // loader coords
    int a_row = tid >> 3;            // base row 0..31 (x4 iters covers 128)
    int a_kq  = (tid & 7) * 4;       // k word offset
    int b_kr  = tid >> 4;            // base k-row 0..15 (x2 iters covers 32)
    int b_nq  = (tid & 15) * 4;      // n word offset

    auto load_tile = [&](int buf, int k0) {
        float* As = smem + buf * AS_WORDS;
        float* Bs = smem + 2 * AS_WORDS + buf * BS_WORDS;
#pragma unroll
        for (int i = 0; i < 4; i++) {
            int row = a_row + i * 32;
            cp16(&As[row * AS_STRIDE + a_kq],
                 A + (long)(mb + row) * K + k0 + a_kq, (mb + row) < M);
        }
#pragma unroll
        for (int i = 0; i < 2; i++) {
            int kr = b_kr + i * 16;
            cp16(&Bs[kr * BS_STRIDE + b_nq],
                 B + (long)(k0 + kr) * Nh + ncol + b_nq, true);
        }
        asm volatile("cp.async.commit_group;\n" ::);
    };

    int nt = K / BK;
    load_tile(0, 0);
    for (int kt = 0; kt < nt; kt++) {
        if (kt + 1 < nt) {
            load_tile((kt + 1) & 1, (kt + 1) * BK);
            asm volatile("cp.async.wait_group 1;\n" ::);
        } else {
            asm volatile("cp.async.wait_group 0;\n" ::);
        }
        __syncthreads();
        const float* As = smem + (kt & 1) * AS_WORDS;
        const float* Bs = smem + 2 * AS_WORDS + (kt & 1) * BS_WORDS;
#pragma unroll
        for (int ks = 0; ks < 4; ks++) {
            int kk = ks * 8;
            uint32_t a[2][4], b[4][2];
#pragma unroll
            for (int im = 0; im < 2; im++) {
                int r0 = wm + im * 16 + g;
                a[im][0] = __float_as_uint(As[r0 * AS_STRIDE + kk + t]);
                a[im][1] = __float_as_uint(As[(r0 + 8) * AS_STRIDE + kk + t]);
                a[im][2] = __float_as_uint(As[r0 * AS_STRIDE + kk + t + 4]);
                a[im][3] = __float_as_uint(As[(r0 + 8) * AS_STRIDE + kk + t + 4]);
            }
#pragma unroll
            for (int jn = 0; jn < 4; jn++) {
                int col = wn + jn * 8 + g;
                b[jn][0] = __float_as_uint(Bs[(kk + t) * BS_STRIDE + col]);
                b[jn][1] = __float_as_uint(Bs[(kk + t + 4) * BS_STRIDE + col]);
            }
#pragma unroll
            for (int im = 0; im < 2; im++)
#pragma unroll
                for (int jn = 0; jn < 4; jn++)
                    mma_tf32(c[im][jn], a[im], b[jn]);
        }
        __syncthreads();
    }

#pragma unroll
    for (int im = 0; im < 2; im++) {
#pragma unroll
        for (int jn = 0; jn < 4; jn++) {
            int col = nb + wn + jn * 8 + t * 2;
            int row0 = mb + wm + im * 16 + g;
            if (row0 < M)
                *reinterpret_cast<float2*>(&C[(long)row0 * Ntot + col]) =
                    make_float2(c[im][jn][0], c[im][jn][1]);
            int row1 = row0 + 8;
            if (row1 < M)
                *reinterpret_cast<float2*>(&C[(long)row1 * Ntot + col]) =
                    make_float2(c[im][jn][2], c[im][jn][3]);
        }
    }
}

// ---------------- fused GATv2 aggregation per destination node ----------------
// proj: [N, stride] where cols [0, stride/2) = fs, [stride/2, stride) = fd.
template <int D>
__global__ void gat_agg_kernel(const float* __restrict__ proj,
                               const float* __restrict__ attn, const float* __restrict__ bias,
                               const int* __restrict__ rowptr, const int* __restrict__ csrsrc,
                               float* __restrict__ hout, int stride) {
    constexpr int VPT = D / 32;
    int v = blockIdx.x;
    int h = threadIdx.x >> 5;
    int lane = threadIdx.x & 31;
    int fdoff = stride >> 1;

    float fdv[VPT], at[VPT], acc[VPT];
    long vb = (long)v * stride + fdoff + h * D;
#pragma unroll
    for (int j = 0; j < VPT; j++) {
        int d = j * 32 + lane;
        fdv[j] = proj[vb + d];
        at[j]  = attn[h * D + d];
        acc[j] = 0.f;
    }
    float m = -INFINITY, s = 0.f;

    int e0 = rowptr[v], e1 = rowptr[v + 1];
    for (int e = e0; e < e1; e++) {
        int u = csrsrc[e];
        long ub = (long)u * stride + h * D;
        float x[VPT];
        float p = 0.f;
#pragma unroll
        for (int j = 0; j < VPT; j++) {
            int d = j * 32 + lane;
            x[j] = proj[ub + d];
            float tt = x[j] + fdv[j];
            tt = (tt > 0.f) ? tt : 0.2f * tt;   // GATv2 internal leaky_relu
            p += tt * at[j];
        }
#pragma unroll
        for (int off = 16; off; off >>= 1)
            p += __shfl_xor_sync(0xffffffffu, p, off);
        if (p > m) {
            float cc = __expf(m - p);
            s = s * cc + 1.f;
#pragma unroll
            for (int j = 0; j < VPT; j++) acc[j] = acc[j] * cc + x[j];
            m = p;
        } else {
            float w = __expf(p - m);
            s += w;
#pragma unroll
            for (int j = 0; j < VPT; j++) acc[j] += w * x[j];
        }
    }

    __shared__ float hm[HH][D];
    float inv_s = (e1 > e0) ? (1.f / s) : 0.f;
#pragma unroll
    for (int j = 0; j < VPT; j++) {
        int d = j * 32 + lane;
        hm[h][d] = acc[j] * inv_s + bias[h * D + d];
    }
    __syncthreads();
    for (int d = threadIdx.x; d < D; d += blockDim.x) {
        float mv = 0.25f * (hm[0][d] + hm[1][d] + hm[2][d] + hm[3][d]);
        mv = (mv > 0.f) ? mv : 0.01f * mv;      // ACT leaky_relu
        hout[(long)v * D + d] = tf32r(mv);      // pre-round for next GEMM
    }
}

// ---------------- final mean over nodes: [N,64] -> [64] ----------------
__global__ void final_mean_kernel(const float* __restrict__ hin, float* __restrict__ out, int n) {
    int d = threadIdx.x;  // blockDim = 64
    float sum = 0.f;
    for (int r = blockIdx.x; r < n; r += gridDim.x)
        sum += hin[(long)r * 64 + d];
    atomicAdd(&out[d], sum * (1.0f / (float)NN));
}

// ---------------- launch ----------------
extern "C" void kernel_launch(void* const* d_in, const int* in_sizes, int n_in,
                              void* d_out, int out_size) {
    const float* n_feat = (const float*)d_in[0];
    const int*   src    = (const int*)d_in[1];
    const int*   dst    = (const int*)d_in[2];
    const float* Wl0 = (const float*)d_in[3];
    const float* Wr0 = (const float*)d_in[4];
    const float* attn0 = (const float*)d_in[5];
    const float* b0 = (const float*)d_in[6];
    const float* Wl1 = (const float*)d_in[7];
    const float* Wr1 = (const float*)d_in[8];
    const float* attn1 = (const float*)d_in[9];
    const float* b1 = (const float*)d_in[10];
    const float* Wl2 = (const float*)d_in[11];
    const float* Wr2 = (const float*)d_in[12];
    const float* attn2 = (const float*)d_in[13];
    const float* b2 = (const float*)d_in[14];
    float* out = (float*)d_out;

    float *proj, *A0, *h1, *h2, *wbuf;
    int *cnt, *cursor, *rowptr, *csrsrc;
    cudaGetSymbolAddress((void**)&proj, g_proj);
    cudaGetSymbolAddress((void**)&A0, g_A0);
    cudaGetSymbolAddress((void**)&h1, g_h1);
    cudaGetSymbolAddress((void**)&h2, g_h2);
    cudaGetSymbolAddress((void**)&wbuf, g_wbuf);
    cudaGetSymbolAddress((void**)&cnt, g_cnt);
    cudaGetSymbolAddress((void**)&cursor, g_cursor);
    cudaGetSymbolAddress((void**)&rowptr, g_rowptr);
    cudaGetSymbolAddress((void**)&csrsrc, g_csrsrc);

    cudaFuncSetAttribute(gemm_tc2_kernel,
                         cudaFuncAttributeMaxDynamicSharedMemorySize, SMEM_BYTES);

    const int N = NN, E = EE;

    // CSR build
    cudaMemsetAsync(cnt, 0, N * sizeof(int));
    cudaMemsetAsync(cursor, 0, N * sizeof(int));
    hist_kernel<<<(E + 255) / 256, 256>>>(dst, cnt, E);
    scan_kernel<<<1, 1024>>>(cnt, rowptr, N);
    scatter_kernel<<<(E + 255) / 256, 256>>>(src, dst, rowptr, cursor, csrsrc, E);

    // tf32 pre-rounding of A (layer 0) and all weights
    auto rnd = [&](const float* in, float* outp, int n) {
        tf32_round_kernel<<<(n / 4 + 255) / 256, 256>>>(in, outp, n);
    };
    rnd(n_feat, A0, NN * 512);
    rnd(Wl0, wbuf + OFF_WL0, 512 * 512);
    rnd(Wr0, wbuf + OFF_WR0, 512 * 512);
    rnd(Wl1, wbuf + OFF_WL1, 128 * 512);
    rnd(Wr1, wbuf + OFF_WR1, 128 * 512);
    rnd(Wl2, wbuf + OFF_WL2, 128 * 256);
    rnd(Wr2, wbuf + OFF_WR2, 128 * 256);

    dim3 tb(256);
    int mblk = (N + BM - 1) / BM;

    // ---- layer 0: 512 -> H x 128 ----
    gemm_tc2_kernel<<<dim3(1024 / BN, mblk), tb, SMEM_BYTES>>>(
        A0, wbuf + OFF_WL0, wbuf + OFF_WR0, proj, N, 512, 512);
    gat_agg_kernel<128><<<N, 128>>>(proj, attn0, b0, rowptr, csrsrc, h1, 1024);

    // ---- layer 1: 128 -> H x 128 ----
    gemm_tc2_kernel<<<dim3(1024 / BN, mblk), tb, SMEM_BYTES>>>(
        h1, wbuf + OFF_WL1, wbuf + OFF_WR1, proj, N, 512, 128);
    gat_agg_kernel<128><<<N, 128>>>(proj, attn1, b1, rowptr, csrsrc, h2, 1024);

    // ---- layer 2 (output): 128 -> H x 64 ----
    gemm_tc2_kernel<<<dim3(512 / BN, mblk), tb, SMEM_BYTES>>>(
        h2, wbuf + OFF_WL2, wbuf + OFF_WR2, proj, N, 256, 128);
    gat_agg_kernel<64><<<N, 128>>>(proj, attn2, b2, rowptr, csrsrc, h1, 512);

    // ---- readout ----
    cudaMemsetAsync(out, 0, 64 * sizeof(float));
    final_mean_kernel<<<256, 64>>>(h1, out, N);
}

// round 4
// speedup vs baseline: 1.9133x; 1.0168x over previous
#include <cuda_runtime.h>
#include <cuda_bf16.h>
#include <math.h>
#include <stdint.h>

// Problem constants
#define NN   20000
#define EE   320000
#define HH   4

// ---------------- scratch (static __device__, no allocs) ----------------
__device__ float g_proj[NN * 1024];    // combined [fs | fd] projections
__device__ float g_A0[NN * 512];       // tf32-rounded n_feat
__device__ float g_h1[NN * 128];
__device__ float g_h2[NN * 128];
__device__ float g_wbuf[720896];       // tf32-rounded weights, packed
__device__ int   g_cnt[NN];
__device__ int   g_cursor[NN];
__device__ int   g_rowptr[NN + 1];
__device__ int   g_csrsrc[EE];

#define OFF_WL0 0
#define OFF_WR0 262144
#define OFF_WL1 524288
#define OFF_WR1 589824
#define OFF_WL2 655360
#define OFF_WR2 688128

__device__ __forceinline__ uint32_t f2tf32(float x) {
    uint32_t r;
    asm("cvt.rna.tf32.f32 %0, %1;" : "=r"(r) : "f"(x));
    return r;
}
__device__ __forceinline__ float tf32r(float x) { return __uint_as_float(f2tf32(x)); }

// ---------------- tf32 pre-rounding ----------------
__global__ void tf32_round_kernel(const float* __restrict__ in, float* __restrict__ out, int n) {
    int i = (blockIdx.x * blockDim.x + threadIdx.x) * 4;
    if (i < n) {
        float4 v = *reinterpret_cast<const float4*>(in + i);
        v.x = tf32r(v.x); v.y = tf32r(v.y); v.z = tf32r(v.z); v.w = tf32r(v.w);
        *reinterpret_cast<float4*>(out + i) = v;
    }
}

// ---------------- CSR build ----------------
__global__ void hist_kernel(const int* __restrict__ dst, int* __restrict__ cnt, int E) {
    int e = blockIdx.x * blockDim.x + threadIdx.x;
    if (e < E) atomicAdd(&cnt[dst[e]], 1);
}

__global__ void scan_kernel(const int* __restrict__ cnt, int* __restrict__ rowptr, int n) {
    __shared__ int smem[1024];
    __shared__ int carry;
    int tid = threadIdx.x;
    if (tid == 0) { carry = 0; rowptr[0] = 0; }
    __syncthreads();
    for (int base = 0; base < n; base += 1024) {
        int c = carry;
        __syncthreads();
        int i = base + tid;
        int v = (i < n) ? cnt[i] : 0;
        smem[tid] = v;
        __syncthreads();
        for (int off = 1; off < 1024; off <<= 1) {
            int t = (tid >= off) ? smem[tid - off] : 0;
            __syncthreads();
            smem[tid] += t;
            __syncthreads();
        }
        if (i < n) rowptr[i + 1] = smem[tid] + c;
        __syncthreads();
        if (tid == 0) carry = c + smem[1023];
        __syncthreads();
    }
}

__global__ void scatter_kernel(const int* __restrict__ src, const int* __restrict__ dst,
                               const int* __restrict__ rowptr, int* __restrict__ cursor,
                               int* __restrict__ csrsrc, int E) {
    int e = blockIdx.x * blockDim.x + threadIdx.x;
    if (e < E) {
        int d = dst[e];
        int pos = rowptr[d] + atomicAdd(&cursor[d], 1);
        csrsrc[pos] = src[e];
    }
}

// ---------------- TF32 tensor-core GEMM, cp.async double-buffered ----------------
// C[M, 2*Nh] = A[M,K] @ [Bl | Br], row-major, pre-rounded tf32.
// BM=128, BN=128, BK=32. 256 threads = 8 warps (4m x 2n), warp tile 32x64.
#define BM 128
#define BN 128
#define BK 32
#define AS_STRIDE 36    // banks for A frags: 4g+t (bijective)
#define BS_STRIDE 136   // 136 % 32 == 8 -> banks 8t+g (bijective)
#define AS_WORDS (BM * AS_STRIDE)   // 4608
#define BS_WORDS (BK * BS_STRIDE)   // 4352
#define SMEM_BYTES ((2 * AS_WORDS + 2 * BS_WORDS) * 4)   // 71680

__device__ __forceinline__ void cp16(float* dst, const float* src, bool p) {
    uint32_t d = (uint32_t)__cvta_generic_to_shared(dst);
    int sz = p ? 16 : 0;
    asm volatile("cp.async.cg.shared.global [%0], [%1], 16, %2;\n" :: "r"(d), "l"(src), "r"(sz));
}

__device__ __forceinline__ void mma_tf32(float* d, const uint32_t* a, const uint32_t* b) {
    asm volatile(
        "mma.sync.aligned.m16n8k8.row.col.f32.tf32.tf32.f32 "
        "{%0,%1,%2,%3}, {%4,%5,%6,%7}, {%8,%9}, {%0,%1,%2,%3};\n"
        : "+f"(d[0]), "+f"(d[1]), "+f"(d[2]), "+f"(d[3])
        : "r"(a[0]), "r"(a[1]), "r"(a[2]), "r"(a[3]), "r"(b[0]), "r"(b[1]));
}

__global__ __launch_bounds__(256) void gemm_tc2_kernel(
        const float* __restrict__ A, const float* __restrict__ Bl,
        const float* __restrict__ Br, float* __restrict__ C,
        int M, int Nh, int K) {
    extern __shared__ float smem[];
    const int Ntot = 2 * Nh;

    int tid  = threadIdx.x;
    int warp = tid >> 5, lane = tid & 31;
    int g = lane >> 2, t = lane & 3;
    int mb = blockIdx.y * BM;
    int nb = blockIdx.x * BN;
    const float* B = (nb < Nh) ? Bl : Br;
    int ncol = (nb < Nh) ? nb : nb - Nh;
    int wm = (warp & 3) * 32, wn = (warp >> 2) * 64;

    float c[2][8][4];
#pragma unroll
    for (int i = 0; i < 2; i++)
#pragma unroll
        for (int j = 0; j < 8; j++)
#pragma unroll
            for (int r = 0; r < 4; r++) c[i][j][r] = 0.f;

    // loader coords: A 128 rows x 8 float4 (1024 cp/tile, 4/thread)
    int a_row = tid >> 3;            // 0..31 (x4 -> 128)
    int a_kq  = (tid & 7) * 4;
    // B: 32 k-rows x 32 float4 (1024 cp/tile, 4/thread)
    int b_kr  = tid >> 3;            // 0..31
    int b_nq  = (tid & 7) * 4;       // word offset (x4 iters -> +32 each)

    auto load_tile = [&](int buf, int k0) {
        float* As = smem + buf * AS_WORDS;
        float* Bs = smem + 2 * AS_WORDS + buf * BS_WORDS;
#pragma unroll
        for (int i = 0; i < 4; i++) {
            int row = a_row + i * 32;
            cp16(&As[row * AS_STRIDE + a_kq],
                 A + (long)(mb + row) * K + k0 + a_kq, (mb + row) < M);
        }
#pragma unroll
        for (int i = 0; i < 4; i++) {
            int nq = b_nq + i * 32;
            cp16(&Bs[b_kr * BS_STRIDE + nq],
                 B + (long)(k0 + b_kr) * Nh + ncol + nq, true);
        }
        asm volatile("cp.async.commit_group;\n" ::);
    };

    int nt = K / BK;
    load_tile(0, 0);
    for (int kt = 0; kt < nt; kt++) {
        if (kt + 1 < nt) {
            load_tile((kt + 1) & 1, (kt + 1) * BK);
            asm volatile("cp.async.wait_group 1;\n" ::);
        } else {
            asm volatile("cp.async.wait_group 0;\n" ::);
        }
        __syncthreads();
        const float* As = smem + (kt & 1) * AS_WORDS;
        const float* Bs = smem + 2 * AS_WORDS + (kt & 1) * BS_WORDS;
#pragma unroll
        for (int ks = 0; ks < 4; ks++) {
            int kk = ks * 8;
            uint32_t a[2][4], b[8][2];
#pragma unroll
            for (int im = 0; im < 2; im++) {
                int r0 = wm + im * 16 + g;
                a[im][0] = __float_as_uint(As[r0 * AS_STRIDE + kk + t]);
                a[im][1] = __float_as_uint(As[(r0 + 8) * AS_STRIDE + kk + t]);
                a[im][2] = __float_as_uint(As[r0 * AS_STRIDE + kk + t + 4]);
                a[im][3] = __float_as_uint(As[(r0 + 8) * AS_STRIDE + kk + t + 4]);
            }
#pragma unroll
            for (int jn = 0; jn < 8; jn++) {
                int col = wn + jn * 8 + g;
                b[jn][0] = __float_as_uint(Bs[(kk + t) * BS_STRIDE + col]);
                b[jn][1] = __float_as_uint(Bs[(kk + t + 4) * BS_STRIDE + col]);
            }
#pragma unroll
            for (int im = 0; im < 2; im++)
#pragma unroll
                for (int jn = 0; jn < 8; jn++)
                    mma_tf32(c[im][jn], a[im], b[jn]);
        }
        __syncthreads();
    }

#pragma unroll
    for (int im = 0; im < 2; im++) {
#pragma unroll
        for (int jn = 0; jn < 8; jn++) {
            int col = nb + wn + jn * 8 + t * 2;
            int row0 = mb + wm + im * 16 + g;
            if (row0 < M)
                *reinterpret_cast<float2*>(&C[(long)row0 * Ntot + col]) =
                    make_float2(c[im][jn][0], c[im][jn][1]);
            int row1 = row0 + 8;
            if (row1 < M)
                *reinterpret_cast<float2*>(&C[(long)row1 * Ntot + col]) =
                    make_float2(c[im][jn][2], c[im][jn][3]);
        }
    }
}

// ---------------- fused GATv2 aggregation ----------------
// Lane owns VPT *contiguous* dims -> single vector load per edge per warp.
template <int VPT>
__device__ __forceinline__ void vload(float* x, const float* p);
template <>
__device__ __forceinline__ void vload<4>(float* x, const float* p) {
    float4 v = *reinterpret_cast<const float4*>(p);
    x[0] = v.x; x[1] = v.y; x[2] = v.z; x[3] = v.w;
}
template <>
__device__ __forceinline__ void vload<2>(float* x, const float* p) {
    float2 v = *reinterpret_cast<const float2*>(p);
    x[0] = v.x; x[1] = v.y;
}

template <int D>
__global__ void gat_agg_kernel(const float* __restrict__ proj,
                               const float* __restrict__ attn, const float* __restrict__ bias,
                               const int* __restrict__ rowptr, const int* __restrict__ csrsrc,
                               float* __restrict__ hout, int stride) {
    constexpr int VPT = D / 32;
    int v = blockIdx.x;
    int h = threadIdx.x >> 5;
    int lane = threadIdx.x & 31;
    int dbase = lane * VPT;                 // contiguous dims per lane
    int fdoff = stride >> 1;

    float fdv[VPT], at[VPT], acc[VPT];
    vload<VPT>(fdv, proj + (long)v * stride + fdoff + h * D + dbase);
    vload<VPT>(at,  attn + h * D + dbase);
#pragma unroll
    for (int j = 0; j < VPT; j++) acc[j] = 0.f;

    float m = -INFINITY, s = 0.f;

    int e0 = rowptr[v], e1 = rowptr[v + 1];
    if (e0 < e1) {
        int u = csrsrc[e0];
        float x[VPT];
        vload<VPT>(x, proj + (long)u * stride + h * D + dbase);
        for (int e = e0; e < e1; e++) {
            // prefetch next edge
            float xn[VPT];
            int en = (e + 1 < e1) ? e + 1 : e;
            int un = csrsrc[en];
            vload<VPT>(xn, proj + (long)un * stride + h * D + dbase);

            float p = 0.f;
#pragma unroll
            for (int j = 0; j < VPT; j++) {
                float tt = x[j] + fdv[j];
                tt = fmaxf(tt, 0.2f * tt);     // leaky_relu, slope 0.2
                p = fmaf(tt, at[j], p);
            }
#pragma unroll
            for (int off = 16; off; off >>= 1)
                p += __shfl_xor_sync(0xffffffffu, p, off);

            float mn = fmaxf(m, p);
            float corr = __expf(m - mn);       // 0 on first edge (m=-inf)
            float w = __expf(p - mn);
            s = s * corr + w;
#pragma unroll
            for (int j = 0; j < VPT; j++)
                acc[j] = fmaf(acc[j], corr, w * x[j]);
            m = mn;
#pragma unroll
            for (int j = 0; j < VPT; j++) x[j] = xn[j];
        }
    }

    __shared__ float hm[HH][D];
    float inv_s = (e1 > e0) ? (1.f / s) : 0.f;
#pragma unroll
    for (int j = 0; j < VPT; j++)
        hm[h][dbase + j] = fmaf(acc[j], inv_s, bias[h * D + dbase + j]);
    __syncthreads();
    for (int d = threadIdx.x; d < D; d += blockDim.x) {
        float mv = 0.25f * (hm[0][d] + hm[1][d] + hm[2][d] + hm[3][d]);
        mv = fmaxf(mv, 0.01f * mv);            // ACT leaky_relu
        hout[(long)v * D + d] = tf32r(mv);     // pre-round for next GEMM
    }
}

// ---------------- final mean over nodes ----------------
__global__ void final_mean_kernel(const float* __restrict__ hin, float* __restrict__ out, int n) {
    int d = threadIdx.x;  // blockDim = 64
    float sum = 0.f;
    for (int r = blockIdx.x; r < n; r += gridDim.x)
        sum += hin[(long)r * 64 + d];
    atomicAdd(&out[d], sum * (1.0f / (float)NN));
}

// ---------------- launch ----------------
extern "C" void kernel_launch(void* const* d_in, const int* in_sizes, int n_in,
                              void* d_out, int out_size) {
    const float* n_feat = (const float*)d_in[0];
    const int*   src    = (const int*)d_in[1];
    const int*   dst    = (const int*)d_in[2];
    const float* Wl0 = (const float*)d_in[3];
    const float* Wr0 = (const float*)d_in[4];
    const float* attn0 = (const float*)d_in[5];
    const float* b0 = (const float*)d_in[6];
    const float* Wl1 = (const float*)d_in[7];
    const float* Wr1 = (const float*)d_in[8];
    const float* attn1 = (const float*)d_in[9];
    const float* b1 = (const float*)d_in[10];
    const float* Wl2 = (const float*)d_in[11];
    const float* Wr2 = (const float*)d_in[12];
    const float* attn2 = (const float*)d_in[13];
    const float* b2 = (const float*)d_in[14];
    float* out = (float*)d_out;

    float *proj, *A0, *h1, *h2, *wbuf;
    int *cnt, *cursor, *rowptr, *csrsrc;
    cudaGetSymbolAddress((void**)&proj, g_proj);
    cudaGetSymbolAddress((void**)&A0, g_A0);
    cudaGetSymbolAddress((void**)&h1, g_h1);
    cudaGetSymbolAddress((void**)&h2, g_h2);
    cudaGetSymbolAddress((void**)&wbuf, g_wbuf);
    cudaGetSymbolAddress((void**)&cnt, g_cnt);
    cudaGetSymbolAddress((void**)&cursor, g_cursor);
    cudaGetSymbolAddress((void**)&rowptr, g_rowptr);
    cudaGetSymbolAddress((void**)&csrsrc, g_csrsrc);

    cudaFuncSetAttribute(gemm_tc2_kernel,
                         cudaFuncAttributeMaxDynamicSharedMemorySize, SMEM_BYTES);

    const int N = NN, E = EE;

    // CSR build
    cudaMemsetAsync(cnt, 0, N * sizeof(int));
    cudaMemsetAsync(cursor, 0, N * sizeof(int));
    hist_kernel<<<(E + 255) / 256, 256>>>(dst, cnt, E);
    scan_kernel<<<1, 1024>>>(cnt, rowptr, N);
    scatter_kernel<<<(E + 255) / 256, 256>>>(src, dst, rowptr, cursor, csrsrc, E);

    // tf32 pre-rounding
    auto rnd = [&](const float* in, float* outp, int n) {
        tf32_round_kernel<<<(n / 4 + 255) / 256, 256>>>(in, outp, n);
    };
    rnd(n_feat, A0, NN * 512);
    rnd(Wl0, wbuf + OFF_WL0, 512 * 512);
    rnd(Wr0, wbuf + OFF_WR0, 512 * 512);
    rnd(Wl1, wbuf + OFF_WL1, 128 * 512);
    rnd(Wr1, wbuf + OFF_WR1, 128 * 512);
    rnd(Wl2, wbuf + OFF_WL2, 128 * 256);
    rnd(Wr2, wbuf + OFF_WR2, 128 * 256);

    dim3 tb(256);
    int mblk = (N + BM - 1) / BM;

    // ---- layer 0: 512 -> H x 128 ----
    gemm_tc2_kernel<<<dim3(1024 / BN, mblk), tb, SMEM_BYTES>>>(
        A0, wbuf + OFF_WL0, wbuf + OFF_WR0, proj, N, 512, 512);
    gat_agg_kernel<128><<<N, 128>>>(proj, attn0, b0, rowptr, csrsrc, h1, 1024);

    // ---- layer 1: 128 -> H x 128 ----
    gemm_tc2_kernel<<<dim3(1024 / BN, mblk), tb, SMEM_BYTES>>>(
        h1, wbuf + OFF_WL1, wbuf + OFF_WR1, proj, N, 512, 128);
    gat_agg_kernel<128><<<N, 128>>>(proj, attn1, b1, rowptr, csrsrc, h2, 1024);

    // ---- layer 2 (output): 128 -> H x 64 ----
    gemm_tc2_kernel<<<dim3(512 / BN, mblk), tb, SMEM_BYTES>>>(
        h2, wbuf + OFF_WL2, wbuf + OFF_WR2, proj, N, 256, 128);
    gat_agg_kernel<64><<<N, 128>>>(proj, attn2, b2, rowptr, csrsrc, h1, 512);

    // ---- readout ----
    cudaMemsetAsync(out, 0, 64 * sizeof(float));
    final_mean_kernel<<<256, 64>>>(h1, out, N);
}